// round 17
// baseline (speedup 1.0000x reference)
#include <cuda_runtime.h>
#include <stdint.h>
#include <math.h>

// ---------------------------------------------------------------------------
// GraphWaveNet forward, fp32 + packed f32x2 GEMM cores.
// Base: Round-16 passing kernel (2363us).
// Deltas: gcn/skip/end1 GEMMs use pre-duplicated 64-bit B smem (no pack MOVs),
// LDS.128 A loads, column mapping n = tx + 16*j (conflict-free LDS.64).
// ---------------------------------------------------------------------------

#define NLAYER 8
#define BATCH  16
#define NNODE  1024
#define L0     13
#define RC     32
#define DC     32
#define SC     256
#define EC     512
#define OCH    12
#define EMBD   10
#define BN_EPS 1e-5f

typedef unsigned long long ull;

// -------------------- device scratch (allocation-free) ---------------------
__device__ float g_adp  [NNODE * NNODE];
__device__ float g_h0   [BATCH * NNODE * L0 * RC];
__device__ float g_h1   [BATCH * NNODE * L0 * RC];
__device__ float g_y    [BATCH * NNODE * 12 * DC];
__device__ float g_glast[BATCH * NNODE * 256];
__device__ float g_skip [BATCH * NNODE * SC];
__device__ float g_c1   [BATCH * NNODE * EC];
__device__ float g_W2   [256 * 256];
__device__ float g_sb2  [256];

// -------------------- packed f32x2 helpers ----------------------------------
__device__ __forceinline__ void ffma2(ull& d, ull a, ull b) {
    asm("fma.rn.f32x2 %0, %1, %2, %0;" : "+l"(d) : "l"(a), "l"(b));
}
__device__ __forceinline__ ull pack2(float lo, float hi) {
    ull u;
    asm("mov.b64 %0, {%1, %2};" : "=l"(u) : "f"(lo), "f"(hi));
    return u;
}
__device__ __forceinline__ float lo32(ull u) {
    return __uint_as_float((unsigned)(u & 0xffffffffu));
}
__device__ __forceinline__ float hi32(ull u) {
    return __uint_as_float((unsigned)(u >> 32));
}

// -------------------- adaptive adjacency: softmax(relu(E E^T)) -------------
__global__ void adp_kernel(const float* __restrict__ emb) {
    __shared__ float sE[EMBD];
    __shared__ float sm[NNODE];
    __shared__ float red[256];
    int v = blockIdx.x;
    int tid = threadIdx.x;
    if (tid < EMBD) sE[tid] = emb[v * EMBD + tid];
    __syncthreads();
    float lmax = -1e30f;
    for (int w = tid; w < NNODE; w += 256) {
        float dot = 0.f;
#pragma unroll
        for (int e = 0; e < EMBD; e++) dot += sE[e] * emb[w * EMBD + e];
        dot = fmaxf(dot, 0.f);
        sm[w] = dot;
        lmax = fmaxf(lmax, dot);
    }
    red[tid] = lmax; __syncthreads();
    for (int s = 128; s > 0; s >>= 1) {
        if (tid < s) red[tid] = fmaxf(red[tid], red[tid + s]);
        __syncthreads();
    }
    float mx = red[0]; __syncthreads();
    float lsum = 0.f;
    for (int w = tid; w < NNODE; w += 256) {
        float e = __expf(sm[w] - mx);
        sm[w] = e;
        lsum += e;
    }
    red[tid] = lsum; __syncthreads();
    for (int s = 128; s > 0; s >>= 1) {
        if (tid < s) red[tid] += red[tid + s];
        __syncthreads();
    }
    float inv = 1.0f / red[0];
    for (int w = tid; w < NNODE; w += 256)
        g_adp[v * NNODE + w] = sm[w] * inv;
}

// -------------------- start 1x1 conv (CIN=2 -> RC) --------------------------
__global__ void start_kernel(const float* __restrict__ x,
                             const float* __restrict__ w,
                             const float* __restrict__ b) {
    int idx = blockIdx.x * blockDim.x + threadIdx.x;
    if (idx >= BATCH * NNODE * L0 * RC) return;
    int c = idx & 31;
    int t = idx >> 5;
    int l = t % L0; t /= L0;
    int n = t % NNODE; t /= NNODE;
    int bb = t;
    const float* xp = x + (((size_t)bb * L0 + l) * NNODE + n) * 2;
    g_h0[idx] = w[c * 2 + 0] * xp[0] + w[c * 2 + 1] * xp[1] + b[c];
}

// -------------------- tcn: one warp per (b,n) (R12-proven) ------------------
template<int LIN, int DIL>
__global__ __launch_bounds__(256)
void tcn_fast_kernel(int hin_sel,
                     const float* __restrict__ tcn_w,
                     const float* __restrict__ tcn_b,
                     const float* __restrict__ gcn_w,
                     int layer, int write_y) {
    constexpr int LOUT = LIN - DIL;
    __shared__ float w0s[32][32], w1s[32][32], gws[32][32], sb[32];
    int tid = threadIdx.x;
    for (int i = tid; i < 1024; i += 256) {
        int o = i >> 5, c = i & 31;
        w0s[c][o] = tcn_w[(o * 32 + c) * 2 + 0];
        w1s[c][o] = tcn_w[(o * 32 + c) * 2 + 1];
        gws[c][o] = gcn_w[o * 32 + c];
    }
    if (tid < 32) sb[tid] = tcn_b[tid];
    __syncthreads();

    const float* h_in = hin_sel ? g_h1 : g_h0;
    int lane = tid & 31, warp = tid >> 5;
    int bn = blockIdx.x * 8 + warp;

    const float* hp = h_in + (size_t)bn * (LIN * 32);
    float h[LIN];
#pragma unroll
    for (int l = 0; l < LIN; l++) h[l] = hp[l * 32 + lane];

    float acc[LOUT];
#pragma unroll
    for (int l = 0; l < LOUT; l++) acc[l] = sb[lane];

#pragma unroll
    for (int c = 0; c < 32; c++) {
        float hl[LIN];
#pragma unroll
        for (int l = 0; l < LIN; l++)
            hl[l] = __shfl_sync(0xffffffffu, h[l], c);
        float w0 = w0s[c][lane], w1 = w1s[c][lane];
#pragma unroll
        for (int l = 0; l < LOUT; l++) {
            acc[l] = fmaf(w0, hl[l], acc[l]);
            acc[l] = fmaf(w1, hl[l + DIL], acc[l]);
        }
    }

    float gate[LOUT];
#pragma unroll
    for (int l = 0; l < LOUT; l++)
        gate[l] = tanhf(acc[l]) * (1.0f / (1.0f + __expf(-acc[l])));

    if (write_y) {
        float y[LOUT];
#pragma unroll
        for (int l = 0; l < LOUT; l++) y[l] = 0.f;
#pragma unroll
        for (int c = 0; c < 32; c++) {
            float gw = gws[c][lane];
#pragma unroll
            for (int l = 0; l < LOUT; l++) {
                float gl = __shfl_sync(0xffffffffu, gate[l], c);
                y[l] = fmaf(gw, gl, y[l]);
            }
        }
        float* yp = g_y + (size_t)bn * (LOUT * 32);
#pragma unroll
        for (int l = 0; l < LOUT; l++) yp[l * 32 + lane] = y[l];
    }
    g_glast[(size_t)bn * 256 + layer * 32 + lane] = gate[LOUT - 1];
}

// -------------------- diffusion GEMM + epilogue (f32x2, dup-B) ---------------
// C[w,j] = sum_v adp[v,w] * Y_b[v,j].
// Thread (tx,ty): rows m0+ty*8..+7 (4 packed pairs), cols n0 + tx + 16*j.
#define BM 128
#define BN 64
#define BK 16
__global__ __launch_bounds__(256)
void gcn_gemm_kernel(int hin_sel,
                     const float* __restrict__ gcn_b,
                     const float* __restrict__ bn_g,
                     const float* __restrict__ bn_be,
                     const float* __restrict__ bn_m,
                     const float* __restrict__ bn_v,
                     int L_in, int L_out, int dil) {
    __shared__ float As[BK][BM];
    __shared__ ull   Bs2[BK][BN];
    const float* h_in  = hin_sel ? g_h1 : g_h0;
    float*       h_out = hin_sel ? g_h0 : g_h1;

    int ld = L_out * 32;
    int b  = blockIdx.z;
    int m0 = blockIdx.y * BM;
    int n0 = blockIdx.x * BN;
    int tid = threadIdx.x;
    int tx = tid & 15, ty = tid >> 4;
    const float* Yb = g_y + (size_t)b * NNODE * ld;

    ull acc[4][4];
#pragma unroll
    for (int mi = 0; mi < 4; mi++)
#pragma unroll
        for (int j = 0; j < 4; j++) acc[mi][j] = 0ULL;

    for (int k0 = 0; k0 < NNODE; k0 += BK) {
#pragma unroll
        for (int i = 0; i < 8; i++) {
            int idx = tid + i * 256;
            int k = idx >> 7, m = idx & 127;
            As[k][m] = g_adp[(size_t)(k0 + k) * NNODE + m0 + m];
        }
#pragma unroll
        for (int i = 0; i < 4; i++) {
            int idx = tid + i * 256;
            int k = idx >> 6, n = idx & 63;
            int j = n0 + n;
            float v = (j < ld) ? Yb[(size_t)(k0 + k) * ld + j] : 0.f;
            Bs2[k][n] = pack2(v, v);
        }
        __syncthreads();
#pragma unroll
        for (int k = 0; k < BK; k++) {
            float4 alo = *(const float4*)&As[k][ty * 8];
            float4 ahi = *(const float4*)&As[k][ty * 8 + 4];
            ull a2[4];
            a2[0] = pack2(alo.x, alo.y);
            a2[1] = pack2(alo.z, alo.w);
            a2[2] = pack2(ahi.x, ahi.y);
            a2[3] = pack2(ahi.z, ahi.w);
            ull bd[4];
#pragma unroll
            for (int j = 0; j < 4; j++) bd[j] = Bs2[k][tx + 16 * j];
#pragma unroll
            for (int j = 0; j < 4; j++)
#pragma unroll
                for (int mi = 0; mi < 4; mi++)
                    ffma2(acc[mi][j], a2[mi], bd[j]);
        }
        __syncthreads();
    }

#pragma unroll
    for (int j = 0; j < 4; j++) {
        int jj = n0 + tx + 16 * j;
        if (jj >= ld) continue;
        int l = jj >> 5, r = jj & 31;
        float gb  = gcn_b[r];
        float inv = bn_g[r] * rsqrtf(bn_v[r] + BN_EPS);
        float mu  = bn_m[r], be = bn_be[r];
#pragma unroll
        for (int mi = 0; mi < 4; mi++) {
#pragma unroll
            for (int p = 0; p < 2; p++) {
                int w = m0 + ty * 8 + mi * 2 + p;
                float cv = p ? hi32(acc[mi][j]) : lo32(acc[mi][j]);
                float val = fmaxf(cv + gb, 0.f);
                val += h_in[(((size_t)b * NNODE + w) * L_in + l + dil) * 32 + r];
                val = (val - mu) * inv + be;
                h_out[(((size_t)b * NNODE + w) * L_out + l) * 32 + r] = val;
            }
        }
    }
}

// -------------------- prep: combined skip weights [s][k] + summed bias -----
__global__ void prep_kernel(const float* __restrict__ skip_w,
                            const float* __restrict__ skip_b) {
    int idx = blockIdx.x * blockDim.x + threadIdx.x;
    if (idx < 256 * 256) {
        int s = idx >> 8, k = idx & 255;
        g_W2[idx] = skip_w[(size_t)(k >> 5) * (SC * 32) + s * 32 + (k & 31)];
    } else if (idx < 256 * 256 + 256) {
        int s = idx - 256 * 256;
        float acc = 0.f;
#pragma unroll
        for (int i = 0; i < 8; i++) acc += skip_b[i * 256 + s];
        g_sb2[s] = acc;
    }
}

// -------------------- batched skip GEMM (f32x2, dup-B) ----------------------
__global__ __launch_bounds__(256)
void skip_gemm_kernel() {
    __shared__ float As[BK][BM];
    __shared__ ull   Bs2[BK][BN];
    int m0 = blockIdx.y * BM;
    int n0 = blockIdx.x * BN;
    int tid = threadIdx.x;
    int tx = tid & 15, ty = tid >> 4;

    ull acc[4][4];
#pragma unroll
    for (int mi = 0; mi < 4; mi++)
#pragma unroll
        for (int j = 0; j < 4; j++) acc[mi][j] = 0ULL;

    for (int k0 = 0; k0 < 256; k0 += BK) {
        {
            int m = tid & 127, kh = tid >> 7;
            const float* gp = g_glast + (size_t)(m0 + m) * 256 + k0 + kh * 8;
#pragma unroll
            for (int j = 0; j < 8; j++) As[kh * 8 + j][m] = gp[j];
        }
        {
            int n = tid & 63, kq = tid >> 6;
            const float* wp = g_W2 + (size_t)(n0 + n) * 256 + k0 + kq * 4;
#pragma unroll
            for (int j = 0; j < 4; j++) {
                float v = wp[j];
                Bs2[kq * 4 + j][n] = pack2(v, v);
            }
        }
        __syncthreads();
#pragma unroll
        for (int k = 0; k < BK; k++) {
            float4 alo = *(const float4*)&As[k][ty * 8];
            float4 ahi = *(const float4*)&As[k][ty * 8 + 4];
            ull a2[4];
            a2[0] = pack2(alo.x, alo.y);
            a2[1] = pack2(alo.z, alo.w);
            a2[2] = pack2(ahi.x, ahi.y);
            a2[3] = pack2(ahi.z, ahi.w);
            ull bd[4];
#pragma unroll
            for (int j = 0; j < 4; j++) bd[j] = Bs2[k][tx + 16 * j];
#pragma unroll
            for (int j = 0; j < 4; j++)
#pragma unroll
                for (int mi = 0; mi < 4; mi++)
                    ffma2(acc[mi][j], a2[mi], bd[j]);
        }
        __syncthreads();
    }
#pragma unroll
    for (int j = 0; j < 4; j++) {
        int s = n0 + tx + 16 * j;
        float be = g_sb2[s];
#pragma unroll
        for (int mi = 0; mi < 4; mi++) {
#pragma unroll
            for (int p = 0; p < 2; p++) {
                int pp = m0 + ty * 8 + mi * 2 + p;
                float cv = p ? hi32(acc[mi][j]) : lo32(acc[mi][j]);
                g_skip[(size_t)pp * SC + s] = cv + be;
            }
        }
    }
}

// -------------------- end1: relu(skip) -> 512, relu (f32x2, dup-B) ----------
__global__ __launch_bounds__(256)
void end1_kernel(const float* __restrict__ w, const float* __restrict__ bias) {
    __shared__ float As[BK][BM];
    __shared__ ull   Bs2[BK][BN];
    int m0 = blockIdx.y * BM;
    int n0 = blockIdx.x * BN;
    int tid = threadIdx.x;
    int tx = tid & 15, ty = tid >> 4;

    ull acc[4][4];
#pragma unroll
    for (int mi = 0; mi < 4; mi++)
#pragma unroll
        for (int j = 0; j < 4; j++) acc[mi][j] = 0ULL;

    for (int k0 = 0; k0 < SC; k0 += BK) {
        {
            int m = tid & 127, kh = tid >> 7;
            const float* sp = g_skip + (size_t)(m0 + m) * SC + k0 + kh * 8;
#pragma unroll
            for (int j = 0; j < 8; j++) As[kh * 8 + j][m] = fmaxf(sp[j], 0.f);
        }
        {
            int n = tid & 63, kq = tid >> 6;
            const float* wp = w + (size_t)(n0 + n) * SC + k0 + kq * 4;
#pragma unroll
            for (int j = 0; j < 4; j++) {
                float v = wp[j];
                Bs2[kq * 4 + j][n] = pack2(v, v);
            }
        }
        __syncthreads();
#pragma unroll
        for (int k = 0; k < BK; k++) {
            float4 alo = *(const float4*)&As[k][ty * 8];
            float4 ahi = *(const float4*)&As[k][ty * 8 + 4];
            ull a2[4];
            a2[0] = pack2(alo.x, alo.y);
            a2[1] = pack2(alo.z, alo.w);
            a2[2] = pack2(ahi.x, ahi.y);
            a2[3] = pack2(ahi.z, ahi.w);
            ull bd[4];
#pragma unroll
            for (int j = 0; j < 4; j++) bd[j] = Bs2[k][tx + 16 * j];
#pragma unroll
            for (int j = 0; j < 4; j++)
#pragma unroll
                for (int mi = 0; mi < 4; mi++)
                    ffma2(acc[mi][j], a2[mi], bd[j]);
        }
        __syncthreads();
    }
#pragma unroll
    for (int j = 0; j < 4; j++) {
        int e = n0 + tx + 16 * j;
        float be = bias[e];
#pragma unroll
        for (int mi = 0; mi < 4; mi++) {
#pragma unroll
            for (int p = 0; p < 2; p++) {
                int pp = m0 + ty * 8 + mi * 2 + p;
                float cv = p ? hi32(acc[mi][j]) : lo32(acc[mi][j]);
                g_c1[(size_t)pp * EC + e] = fmaxf(cv + be, 0.f);
            }
        }
    }
}

// -------------------- end2: 512 -> 12, write output (R9-proven) --------------
__global__ __launch_bounds__(128)
void end2_kernel(const float* __restrict__ w, const float* __restrict__ bias,
                 float* __restrict__ out) {
    __shared__ float ws[OCH][EC];
    int tid = threadIdx.x;
    for (int i = tid; i < OCH * EC; i += 128) ws[i / EC][i % EC] = w[i];
    __syncthreads();
    int p = blockIdx.x * 128 + tid;
    if (p >= BATCH * NNODE) return;
    const float* cp = g_c1 + (size_t)p * EC;
    float acc[OCH];
#pragma unroll
    for (int o = 0; o < OCH; o++) acc[o] = bias[o];
    for (int e = 0; e < EC; e += 4) {
        float4 v = *(const float4*)(cp + e);
#pragma unroll
        for (int o = 0; o < OCH; o++) {
            acc[o] = fmaf(ws[o][e + 0], v.x, acc[o]);
            acc[o] = fmaf(ws[o][e + 1], v.y, acc[o]);
            acc[o] = fmaf(ws[o][e + 2], v.z, acc[o]);
            acc[o] = fmaf(ws[o][e + 3], v.w, acc[o]);
        }
    }
#pragma unroll
    for (int o = 0; o < OCH; o++) out[(size_t)p * OCH + o] = acc[o];
}

// ---------------------------------------------------------------------------
extern "C" void kernel_launch(void* const* d_in, const int* in_sizes, int n_in,
                              void* d_out, int out_size) {
    const float* x       = (const float*)d_in[0];
    const float* emb     = (const float*)d_in[1];
    const float* start_w = (const float*)d_in[2];
    const float* start_b = (const float*)d_in[3];
    const float* tcn_w   = (const float*)d_in[4];
    const float* tcn_b   = (const float*)d_in[5];
    const float* skip_w  = (const float*)d_in[6];
    const float* skip_b  = (const float*)d_in[7];
    const float* gcn_w   = (const float*)d_in[8];
    const float* gcn_b   = (const float*)d_in[9];
    const float* bn_g    = (const float*)d_in[10];
    const float* bn_be   = (const float*)d_in[11];
    const float* bn_m    = (const float*)d_in[12];
    const float* bn_v    = (const float*)d_in[13];
    const float* e1w     = (const float*)d_in[14];
    const float* e1b     = (const float*)d_in[15];
    const float* e2w     = (const float*)d_in[16];
    const float* e2b     = (const float*)d_in[17];
    float* out = (float*)d_out;

    adp_kernel<<<NNODE, 256>>>(emb);
    start_kernel<<<(BATCH * NNODE * L0 * RC + 255) / 256, 256>>>(x, start_w, start_b);
    prep_kernel<<<(256 * 256 + 256 + 255) / 256, 256>>>(skip_w, skip_b);

    static const int DIL[NLAYER] = {1, 2, 1, 2, 1, 2, 1, 2};
    const int TCN_GRID = (BATCH * NNODE) / 8;   // 2048
    int L_in = L0;
    int hsel = 0;
    for (int i = 0; i < NLAYER; i++) {
        int d = DIL[i];
        int L_out = L_in - d;
        int last = (i == NLAYER - 1);
        const float* tw = tcn_w + (size_t)i * 32 * 32 * 2;
        const float* tb = tcn_b + (size_t)i * 32;
        const float* gw = gcn_w + (size_t)i * 32 * 32;
        int wy = last ? 0 : 1;
        switch (i) {
        case 0: tcn_fast_kernel<13, 1><<<TCN_GRID, 256>>>(hsel, tw, tb, gw, i, wy); break;
        case 1: tcn_fast_kernel<12, 2><<<TCN_GRID, 256>>>(hsel, tw, tb, gw, i, wy); break;
        case 2: tcn_fast_kernel<10, 1><<<TCN_GRID, 256>>>(hsel, tw, tb, gw, i, wy); break;
        case 3: tcn_fast_kernel< 9, 2><<<TCN_GRID, 256>>>(hsel, tw, tb, gw, i, wy); break;
        case 4: tcn_fast_kernel< 7, 1><<<TCN_GRID, 256>>>(hsel, tw, tb, gw, i, wy); break;
        case 5: tcn_fast_kernel< 6, 2><<<TCN_GRID, 256>>>(hsel, tw, tb, gw, i, wy); break;
        case 6: tcn_fast_kernel< 4, 1><<<TCN_GRID, 256>>>(hsel, tw, tb, gw, i, wy); break;
        case 7: tcn_fast_kernel< 3, 2><<<TCN_GRID, 256>>>(hsel, tw, tb, gw, i, wy); break;
        }
        if (!last) {
            int ld = L_out * 32;
            dim3 gridG((ld + BN - 1) / BN, NNODE / BM, BATCH);
            gcn_gemm_kernel<<<gridG, 256>>>(
                hsel,
                gcn_b + (size_t)i * 32,
                bn_g + (size_t)i * 32, bn_be + (size_t)i * 32,
                bn_m + (size_t)i * 32, bn_v + (size_t)i * 32,
                L_in, L_out, d);
            hsel ^= 1;
        }
        L_in = L_out;
    }

    skip_gemm_kernel<<<dim3(SC / BN, (BATCH * NNODE) / BM), 256>>>();
    end1_kernel<<<dim3(EC / BN, (BATCH * NNODE) / BM), 256>>>(e1w, e1b);
    end2_kernel<<<((BATCH * NNODE) + 127) / 128, 128>>>(e2w, e2b, out);
}